// round 10
// baseline (speedup 1.0000x reference)
#include <cuda_runtime.h>
#include <math.h>

// Problem constants (match reference)
#define NG   50000
#define SV   256          // volume edge
#define BLK  128          // threads per block (one block per Gaussian)

// One block per Gaussian.
// Strategy:
//   1) Recompute bbox exactly as the fp32 JAX reference does (no FMA contraction).
//   2) Separable Gaussian: build 1D weight tables wx[<=16], wy[<=16], wz[<=24]
//      in shared memory (wz padded to 4-aligned groups, with exact-zero weights
//      for voxels outside [loz, hiz) so padded lanes contribute +0.0).
//   3) Inner loop: each work item = (ix, iy, z-group-of-4); one
//      red.global.add.v4.f32 per item (16B-aligned since volume rows are
//      256 floats and group starts are 4-aligned).
__global__ void __launch_bounds__(BLK)
splat_kernel(const float* __restrict__ centers,
             const float* __restrict__ sigmas,
             const float* __restrict__ intensities,
             float* __restrict__ vol)
{
    const int g   = blockIdx.x;
    const int tid = threadIdx.x;

    const float cx  = __ldg(&centers[3 * g + 0]);
    const float cy  = __ldg(&centers[3 * g + 1]);
    const float cz  = __ldg(&centers[3 * g + 2]);
    const float sig = __ldg(&sigmas[g]);
    const float I   = __ldg(&intensities[g]);

    const float k   = 0.5f / (sig * sig);
    // cutoff = (3.0*sigma)*255.0, same op order as reference
    const float cut = __fmul_rn(__fmul_rn(3.0f, sig), 255.0f);

    // Voxel-space center; keep rounding identical to reference (no contraction)
    const float cvx = __fmul_rn(cx, 255.0f);
    const float cvy = __fmul_rn(cy, 255.0f);
    const float cvz = __fmul_rn(cz, 255.0f);

    const int lox = (int)floorf(fmaxf(__fsub_rn(cvx, cut), 0.0f));
    const int loy = (int)floorf(fmaxf(__fsub_rn(cvy, cut), 0.0f));
    const int loz = (int)floorf(fmaxf(__fsub_rn(cvz, cut), 0.0f));
    const int hix = (int)fminf(floorf(fminf(__fadd_rn(cvx, cut), 255.0f)) + 1.0f, 256.0f);
    const int hiy = (int)fminf(floorf(fminf(__fadd_rn(cvy, cut), 255.0f)) + 1.0f, 256.0f);
    const int hiz = (int)fminf(floorf(fminf(__fadd_rn(cvz, cut), 255.0f)) + 1.0f, 256.0f);

    const int wx = hix - lox;                 // >=1, <=14
    const int wy = hiy - loy;                 // >=1, <=14
    const int z0 = loz & ~3;                  // 4-aligned group base, <=252
    const int ngz = ((hiz - 1) - z0) / 4 + 1; // number of z groups, <=5
                                              // last group end = 4-aligned start + 3 <= 255

    __shared__ float wxs[16];
    __shared__ float wys[16];
    __shared__ __align__(16) float wzs[24];

    if (tid < 16) {
        const float d = (float)(lox + tid) / 255.0f - cx;
        wxs[tid] = __expf(-d * d * k);
    } else if (tid < 32) {
        const float d = (float)(loy + (tid - 16)) / 255.0f - cy;
        wys[tid - 16] = __expf(-d * d * k);
    } else if (tid < 56) {
        const int i = tid - 32;
        const int z = z0 + i;
        const float d = (float)z / 255.0f - cz;
        const float w = __expf(-d * d * k);
        // exact zero outside the valid [loz, hiz) range -> padded RED lanes add +0.0
        wzs[i] = (z >= loz && z < hiz) ? w : 0.0f;
    }
    __syncthreads();

    const int total = wx * wy * ngz;          // <= 14*14*5 = 980
    for (int t = tid; t < total; t += BLK) {
        const int gz = t % ngz;
        const int r  = t / ngz;
        const int iy = r % wy;
        const int ix = r / wy;

        const float w = I * wxs[ix] * wys[iy];
        const float4 wz = reinterpret_cast<const float4*>(wzs)[gz];

        const float v0 = w * wz.x;
        const float v1 = w * wz.y;
        const float v2 = w * wz.z;
        const float v3 = w * wz.w;

        float* p = vol + (((lox + ix) * SV + (loy + iy)) * SV + z0 + 4 * gz);
        asm volatile("red.global.add.v4.f32 [%0], {%1,%2,%3,%4};"
                     :: "l"(p), "f"(v0), "f"(v1), "f"(v2), "f"(v3)
                     : "memory");
    }
}

extern "C" void kernel_launch(void* const* d_in, const int* in_sizes, int n_in,
                              void* d_out, int out_size)
{
    const float* centers     = (const float*)d_in[0];   // (N,3) f32
    const float* sigmas      = (const float*)d_in[1];   // (N,)  f32
    const float* intensities = (const float*)d_in[2];   // (N,)  f32
    float* vol = (float*)d_out;                         // 256^3 f32

    // d_out is poisoned before timing; reference output starts from zeros.
    cudaMemsetAsync(d_out, 0, (size_t)out_size * sizeof(float));

    splat_kernel<<<NG, BLK>>>(centers, sigmas, intensities, vol);
}

// round 12
// speedup vs baseline: 1.4069x; 1.4069x over previous
#include <cuda_runtime.h>
#include <math.h>

// Problem constants (match reference)
#define NG   50000
#define SV   256          // volume edge
#define BLK  128          // threads per block (one block per Gaussian)

// One block per Gaussian.
//   1) bbox recomputed with the exact fp32 op order of the JAX reference
//      (no FMA contraction) -> bit-identical integer bounds.
//   2) Separable Gaussian: 1D weight tables in shared.  I is folded into the
//      x-table.  z-table padded to 4-aligned groups with exact-zero weights
//      outside [loz,hiz) so padded RED lanes add +0.0.
//   3) Work loop over xy items only (<=196, uniform magic-mult div by wy);
//      z-groups (<=5, block-uniform count) fully unrolled with the float4
//      weights held in registers.  One red.global.add.v4.f32 per group.
__global__ void __launch_bounds__(BLK)
splat_kernel(const float* __restrict__ centers,
             const float* __restrict__ sigmas,
             const float* __restrict__ intensities,
             float* __restrict__ vol)
{
    const int g   = blockIdx.x;
    const int tid = threadIdx.x;

    const float cx  = __ldg(&centers[3 * g + 0]);
    const float cy  = __ldg(&centers[3 * g + 1]);
    const float cz  = __ldg(&centers[3 * g + 2]);
    const float sig = __ldg(&sigmas[g]);
    const float I   = __ldg(&intensities[g]);

    const float k   = 0.5f / (sig * sig);
    const float cut = __fmul_rn(__fmul_rn(3.0f, sig), 255.0f);

    const float cvx = __fmul_rn(cx, 255.0f);
    const float cvy = __fmul_rn(cy, 255.0f);
    const float cvz = __fmul_rn(cz, 255.0f);

    const int lox = (int)floorf(fmaxf(__fsub_rn(cvx, cut), 0.0f));
    const int loy = (int)floorf(fmaxf(__fsub_rn(cvy, cut), 0.0f));
    const int loz = (int)floorf(fmaxf(__fsub_rn(cvz, cut), 0.0f));
    const int hix = (int)fminf(floorf(fminf(__fadd_rn(cvx, cut), 255.0f)) + 1.0f, 256.0f);
    const int hiy = (int)fminf(floorf(fminf(__fadd_rn(cvy, cut), 255.0f)) + 1.0f, 256.0f);
    const int hiz = (int)fminf(floorf(fminf(__fadd_rn(cvz, cut), 255.0f)) + 1.0f, 256.0f);

    const int wx  = hix - lox;                 // 1..14
    const int wy  = hiy - loy;                 // 1..14
    const int z0  = loz & ~3;                  // 4-aligned, <=252
    const int ngz = ((hiz - 1) - z0) >> 2;     // groups-1: 0..4 (guard count)

    __shared__ float wxs[16];                  // includes intensity factor
    __shared__ float wys[16];
    __shared__ __align__(16) float wzs[24];

    if (tid < 16) {
        const float d = (float)(lox + tid) / 255.0f - cx;
        wxs[tid] = I * __expf(-d * d * k);
    } else if (tid < 32) {
        const float d = (float)(loy + (tid - 16)) / 255.0f - cy;
        wys[tid - 16] = __expf(-d * d * k);
    } else if (tid < 56) {
        const int i = tid - 32;
        const int z = z0 + i;
        const float d = (float)z / 255.0f - cz;
        const float w = __expf(-d * d * k);
        wzs[i] = (z >= loz && z < hiz) ? w : 0.0f;   // exact zero padding
    }
    __syncthreads();

    // Block-uniform z-group weights into registers (groups 0..4 = wzs[0..19]).
    const float4* wz4 = reinterpret_cast<const float4*>(wzs);
    const float4 z4_0 = wz4[0];
    const float4 z4_1 = wz4[1];
    const float4 z4_2 = wz4[2];
    const float4 z4_3 = wz4[3];
    const float4 z4_4 = wz4[4];

    // Exact magic-multiply divide by wy: t < 196, wy <= 16
    const unsigned M = (1u << 20) / (unsigned)wy + 1u;

    float* const base = vol + ((lox * SV + loy) * SV + z0);
    const int nxy = wx * wy;                   // <= 196

#define RED4(P, Z)                                                          \
    asm volatile("red.global.add.v4.f32 [%0], {%1,%2,%3,%4};"               \
                 :: "l"(P), "f"(w * (Z).x), "f"(w * (Z).y),                  \
                    "f"(w * (Z).z), "f"(w * (Z).w) : "memory")

    for (int t = tid; t < nxy; t += BLK) {
        const int ix = (int)(((unsigned)t * M) >> 20);
        const int iy = t - ix * wy;

        const float w = wxs[ix] * wys[iy];
        float* p = base + (ix * (SV * SV) + iy * SV);

        RED4(p, z4_0);
        if (ngz > 0) RED4(p + 4,  z4_1);
        if (ngz > 1) RED4(p + 8,  z4_2);
        if (ngz > 2) RED4(p + 12, z4_3);
        if (ngz > 3) RED4(p + 16, z4_4);
    }
#undef RED4
}

extern "C" void kernel_launch(void* const* d_in, const int* in_sizes, int n_in,
                              void* d_out, int out_size)
{
    const float* centers     = (const float*)d_in[0];   // (N,3) f32
    const float* sigmas      = (const float*)d_in[1];   // (N,)  f32
    const float* intensities = (const float*)d_in[2];   // (N,)  f32
    float* vol = (float*)d_out;                         // 256^3 f32

    cudaMemsetAsync(d_out, 0, (size_t)out_size * sizeof(float));
    splat_kernel<<<NG, BLK>>>(centers, sigmas, intensities, vol);
}